// round 16
// baseline (speedup 1.0000x reference)
#include <cuda_runtime.h>
#include <cuda_fp16.h>
#include <math.h>
#include <stdint.h>

// Problem constants (fixed shapes per metadata)
constexpr int NN   = 10000;   // nodes
constexpr int NE   = 160000;  // edges
constexpr int DIN  = 128;     // input feature dim
constexpr int EDIM = 16;      // edge feature dim
constexpr int H_   = 4;       // heads
constexpr int C_   = 256;     // channels per head
constexpr int HC   = 1024;    // H*C
constexpr int DOUT = 25088;   // final output dim

constexpr int MPAD = 10112;   // 79 * 128 (M padded)
constexpr int NSPL = 5120;    // node/m split point (40 m-blocks)

// ---------------- scratch (static device globals: allocation-free) ----------
__device__ __half g_xw2[NN * HC];         // layer GEMM output (fp16)
__device__ float  g_al_src[NN * H_];
__device__ float  g_al_dst[NN * H_];
__device__ float  g_exp_s[(size_t)H_ * NE];    // exp(alpha-max), SoA CSR-sorted
__device__ float  g_s1[(size_t)H_ * NE];       // raw edge logits layer1 (SoA)
__device__ float  g_s2[(size_t)H_ * NE];       // raw edge logits layer2 (SoA)
__device__ float  g_V1[EDIM * H_];
__device__ float  g_V2[EDIM * H_];
__device__ int    g_deg[NN];
__device__ int    g_rowptr[NN + 1];
__device__ int    g_cursor[NN];
__device__ int    g_esorted[NE];
__device__ int    g_src_s[NE];            // src node per sorted position
__device__ int    g_bsum[40];
__device__ int    g_boff[40];
__device__ __half g_Asp[(size_t)MPAD * HC];     // GEMM A operand (fp16)
__device__ __half g_BtF[(size_t)DOUT * HC];     // Wf^T fp16 [25088,1024]
__device__ __half g_Bt2[(size_t)HC * HC];       // W2^T fp16 [1024,1024]
__device__ __half g_Bt1[(size_t)HC * DIN];      // W1^T fp16 [1024,128]

// ---------------- graph structure kernels ----------------------------------
__global__ void k_zero_deg() {
    int i = blockIdx.x * blockDim.x + threadIdx.x;
    if (i < NN) g_deg[i] = 0;
}

__global__ void k_zero_al() {
    int i = blockIdx.x * blockDim.x + threadIdx.x;
    if (i < NN * H_) { g_al_src[i] = 0.f; g_al_dst[i] = 0.f; }
}

__global__ void k_count(const int* __restrict__ dst) {
    int e = blockIdx.x * blockDim.x + threadIdx.x;
    if (e < NE) atomicAdd(&g_deg[dst[e]], 1);
}

// 3-stage parallel scan of g_deg -> g_rowptr/g_cursor
__global__ void k_scanA() {
    __shared__ int sh[256];
    int i = blockIdx.x * 256 + threadIdx.x;
    sh[threadIdx.x] = (i < NN) ? g_deg[i] : 0;
    __syncthreads();
    for (int off = 128; off; off >>= 1) {
        if (threadIdx.x < off) sh[threadIdx.x] += sh[threadIdx.x + off];
        __syncthreads();
    }
    if (threadIdx.x == 0) g_bsum[blockIdx.x] = sh[0];
}

__global__ void k_scanB() {
    __shared__ int sh[64];
    int t = threadIdx.x;
    int v = (t < 40) ? g_bsum[t] : 0;
    sh[t] = v;
    __syncthreads();
    for (int off = 1; off < 64; off <<= 1) {
        int x = (t >= off) ? sh[t - off] : 0;
        __syncthreads();
        sh[t] += x;
        __syncthreads();
    }
    if (t < 40) g_boff[t] = sh[t] - v;
    if (t == 39) g_rowptr[NN] = sh[39];
}

__global__ void k_scanC() {
    __shared__ int sh[256];
    int i = blockIdx.x * 256 + threadIdx.x;
    int v = (i < NN) ? g_deg[i] : 0;
    sh[threadIdx.x] = v;
    __syncthreads();
    for (int off = 1; off < 256; off <<= 1) {
        int x = (threadIdx.x >= off) ? sh[threadIdx.x - off] : 0;
        __syncthreads();
        sh[threadIdx.x] += x;
        __syncthreads();
    }
    if (i < NN) {
        int excl = sh[threadIdx.x] - v + g_boff[blockIdx.x];
        g_rowptr[i] = excl;
        g_cursor[i] = excl;
    }
}

__global__ void k_fill(const int* __restrict__ dst) {
    int e = blockIdx.x * blockDim.x + threadIdx.x;
    if (e < NE) {
        int p = atomicAdd(&g_cursor[dst[e]], 1);
        g_esorted[p] = e;
    }
}

// ---------------- attention logit pieces ------------------------------------
__global__ void k_V(const float* __restrict__ We, const float* __restrict__ aedge,
                    float* __restrict__ Vout) {
    int w = threadIdx.x >> 5, l = threadIdx.x & 31;
    for (int o = w; o < EDIM * H_; o += 8) {
        int d = o / H_, h = o % H_;
        float s = 0.f;
        for (int c = l; c < C_; c += 32)
            s += We[(size_t)d * HC + h * C_ + c] * aedge[h * C_ + c];
#pragma unroll
        for (int off = 16; off; off >>= 1) s += __shfl_xor_sync(0xffffffffu, s, off);
        if (l == 0) Vout[o] = s;
    }
}

// One pass over CSR-sorted positions (layer-independent): gathers edge
// features once, emits src ids + raw edge logits for BOTH layers.
__global__ void k_edgeprep(const float* __restrict__ ef, const int* __restrict__ src) {
    __shared__ float sV1[EDIM * H_], sV2[EDIM * H_];
    if (threadIdx.x < EDIM * H_) {
        sV1[threadIdx.x] = g_V1[threadIdx.x];
        sV2[threadIdx.x] = g_V2[threadIdx.x];
    }
    __syncthreads();
    int i = blockIdx.x * blockDim.x + threadIdx.x;
    if (i >= NE) return;
    int e  = g_esorted[i];
    g_src_s[i] = src[e];
    float ea[EDIM];
    const float4* efp = reinterpret_cast<const float4*>(ef + (size_t)e * EDIM);
#pragma unroll
    for (int q = 0; q < EDIM / 4; q++) {
        float4 v = efp[q];
        ea[q * 4 + 0] = v.x; ea[q * 4 + 1] = v.y; ea[q * 4 + 2] = v.z; ea[q * 4 + 3] = v.w;
    }
#pragma unroll
    for (int h = 0; h < H_; h++) {
        float s1 = 0.f, s2 = 0.f;
#pragma unroll
        for (int d = 0; d < EDIM; d++) {
            s1 += ea[d] * sV1[d * H_ + h];
            s2 += ea[d] * sV2[d * H_ + h];
        }
        g_s1[(size_t)h * NE + i] = s1;
        g_s2[(size_t)h * NE + i] = s2;
    }
}

// ---------------- segment softmax + aggregation (1 block / node) ------------
// node_base allows node-range splits for stream pipelining.
__global__ void __launch_bounds__(256)
k_aggregate(const __half* __restrict__ xw2, const float* __restrict__ sL,
            const float* __restrict__ bias, __half* __restrict__ outH,
            int node_base) {
    int n = node_base + blockIdx.x;
    int beg = g_rowptr[n], end = g_rowptr[n + 1];
    __shared__ float sm[H_], ss[H_], sself[H_];
    __shared__ float p_es[2][H_], p_mx[2][H_], p_ac[2][H_];
    int t = threadIdx.x, w = t >> 5, l = t & 31;
    const int hh = w & 3, sl = w >> 2;

    // phase 0+1 fused: esum (raw s) + max (leaky alpha) over this warp's slice
    {
        const float* ssrc = sL + (size_t)hh * NE;
        const float ald = g_al_dst[n * H_ + hh];
        float es = 0.f, mx = -1e30f;
        for (int i = beg + l + 32 * sl; i < end; i += 64) {
            float s = ssrc[i];
            es += s;
            float a = g_al_src[g_src_s[i] * H_ + hh] + ald + s;
            a = a > 0.f ? a : 0.2f * a;
            mx = fmaxf(mx, a);
        }
#pragma unroll
        for (int off = 16; off; off >>= 1) {
            es += __shfl_xor_sync(0xffffffffu, es, off);
            mx = fmaxf(mx, __shfl_xor_sync(0xffffffffu, mx, off));
        }
        if (l == 0) { p_es[sl][hh] = es; p_mx[sl][hh] = mx; }
    }
    __syncthreads();
    if (t < H_) {
        float es = p_es[0][t] + p_es[1][t];
        float mx = fmaxf(p_mx[0][t], p_mx[1][t]);
        float invd = 1.0f / fmaxf((float)(end - beg), 1.0f);
        float v = g_al_src[n * H_ + t] + g_al_dst[n * H_ + t] + es * invd;
        v = v > 0.f ? v : 0.2f * v;
        sself[t] = v;
        sm[t] = fmaxf(mx, v);
    }
    __syncthreads();

    // phase 2: recompute alpha, exp, store exp; accumulate sum over slice
    {
        float mm = sm[hh];
        const float* ssrc = sL + (size_t)hh * NE;
        const float ald = g_al_dst[n * H_ + hh];
        float* ex_out = g_exp_s + (size_t)hh * NE;
        float acc = 0.f;
        for (int i = beg + l + 32 * sl; i < end; i += 64) {
            float a = g_al_src[g_src_s[i] * H_ + hh] + ald + ssrc[i];
            a = a > 0.f ? a : 0.2f * a;
            float ex = expf(a - mm);
            ex_out[i] = ex;
            acc += ex;
        }
#pragma unroll
        for (int off = 16; off; off >>= 1) acc += __shfl_xor_sync(0xffffffffu, acc, off);
        if (l == 0) p_ac[sl][hh] = acc;
    }
    __syncthreads();
    if (t < H_)
        ss[t] = p_ac[0][t] + p_ac[1][t] + expf(sself[t] - sm[t]);
    __syncthreads();

    // phase 3: weighted gather, 2-way unrolled (dual dependency chains).
    const int h = t >> 6;
    const float inv = 1.0f / (ss[h] + 1e-16f);
    const float* exh = g_exp_s + (size_t)h * NE;
    float a0 = 0.f, a1 = 0.f, a2 = 0.f, a3 = 0.f;
    float b0 = 0.f, b1v = 0.f, b2v = 0.f, b3 = 0.f;
    int i = beg;
    for (; i + 1 < end; i += 2) {
        int sn0 = g_src_s[i], sn1 = g_src_s[i + 1];
        float w0 = exh[i], w1 = exh[i + 1];
        uint2 r0 = *reinterpret_cast<const uint2*>(xw2 + (size_t)sn0 * HC + 4 * t);
        uint2 r1 = *reinterpret_cast<const uint2*>(xw2 + (size_t)sn1 * HC + 4 * t);
        __half2 p00 = *reinterpret_cast<__half2*>(&r0.x);
        __half2 p01 = *reinterpret_cast<__half2*>(&r0.y);
        __half2 p10 = *reinterpret_cast<__half2*>(&r1.x);
        __half2 p11 = *reinterpret_cast<__half2*>(&r1.y);
        a0 += w0 * __low2float(p00); a1 += w0 * __high2float(p00);
        a2 += w0 * __low2float(p01); a3 += w0 * __high2float(p01);
        b0 += w1 * __low2float(p10); b1v += w1 * __high2float(p10);
        b2v += w1 * __low2float(p11); b3 += w1 * __high2float(p11);
    }
    if (i < end) {
        int sn = g_src_s[i];
        float wg = exh[i];
        uint2 rv = *reinterpret_cast<const uint2*>(xw2 + (size_t)sn * HC + 4 * t);
        __half2 p0 = *reinterpret_cast<__half2*>(&rv.x);
        __half2 p1 = *reinterpret_cast<__half2*>(&rv.y);
        a0 += wg * __low2float(p0); a1 += wg * __high2float(p0);
        a2 += wg * __low2float(p1); a3 += wg * __high2float(p1);
    }
    {   // self loop
        float wg = expf(sself[h] - sm[h]);
        uint2 rv = *reinterpret_cast<const uint2*>(xw2 + (size_t)n * HC + 4 * t);
        __half2 p0 = *reinterpret_cast<__half2*>(&rv.x);
        __half2 p1 = *reinterpret_cast<__half2*>(&rv.y);
        a0 += wg * __low2float(p0); a1 += wg * __high2float(p0);
        a2 += wg * __low2float(p1); a3 += wg * __high2float(p1);
    }
    a0 += b0; a1 += b1v; a2 += b2v; a3 += b3;
    float4 b4 = *reinterpret_cast<const float4*>(bias + 4 * t);
    float v0 = a0 * inv + b4.x, v1 = a1 * inv + b4.y;
    float v2 = a2 * inv + b4.z, v3 = a3 * inv + b4.w;
    v0 = v0 > 0.f ? v0 : expm1f(v0);
    v1 = v1 > 0.f ? v1 : expm1f(v1);
    v2 = v2 > 0.f ? v2 : expm1f(v2);
    v3 = v3 > 0.f ? v3 : expm1f(v3);
    uint2 ov;
    *reinterpret_cast<__half2*>(&ov.x) = __floats2half2_rn(v0, v1);
    *reinterpret_cast<__half2*>(&ov.y) = __floats2half2_rn(v2, v3);
    *reinterpret_cast<uint2*>(outH + (size_t)n * HC + 4 * t) = ov;
}

// ---------------- fp16 conversions ------------------------------------------
__global__ void k_convA(const float* __restrict__ src, __half* __restrict__ dst,
                        int Mv, int K) {
    int i = blockIdx.x * blockDim.x + threadIdx.x;
    if (i >= MPAD * K) return;
    int m = i / K, k = i - m * K;
    float a = (m < Mv) ? src[(size_t)m * K + k] : 0.f;
    dst[(size_t)m * K + k] = __float2half(a);
}

__global__ void k_convB(const float* __restrict__ W, __half* __restrict__ dst,
                        int K, int Nn) {
    __shared__ float t[32][33];
    int n = blockIdx.x * 32 + threadIdx.x;
    int k = blockIdx.y * 32 + threadIdx.y;
    t[threadIdx.y][threadIdx.x] = W[(size_t)k * Nn + n];
    __syncthreads();
    int n2 = blockIdx.x * 32 + threadIdx.y;
    int k2 = blockIdx.y * 32 + threadIdx.x;
    dst[(size_t)n2 * K + k2] = __float2half(t[threadIdx.x][threadIdx.y]);
}

// ---------------- fp16 HMMA GEMM --------------------------------------------
// CTA tile 128x128, 128 threads (4 warps, warp tile 64x64), BK=32,
// 4-stage cp.async pipeline (64 KB smem), 2 CTAs/SM.
// AL=true fuses al_src/al_dst accumulation.  m_base allows m-range splits.

__device__ __forceinline__ uint32_t s2u(const void* p) {
    uint32_t a;
    asm("{ .reg .u64 t; cvta.to.shared.u64 t, %1; cvt.u32.u64 %0, t; }" : "=r"(a) : "l"(p));
    return a;
}

__device__ __forceinline__ void cp16(uint32_t saddr, const void* gptr) {
    asm volatile("cp.async.cg.shared.global [%0], [%1], 16;" :: "r"(saddr), "l"(gptr));
}

#define LDSM4(r, addr) \
    asm volatile("ldmatrix.sync.aligned.m8n8.x4.shared.b16 {%0,%1,%2,%3}, [%4];" \
        : "=r"((r)[0]), "=r"((r)[1]), "=r"((r)[2]), "=r"((r)[3]) : "r"(addr))

#define MMA16816(c, a, b0, b1) \
    asm volatile("mma.sync.aligned.m16n8k16.row.col.f32.f16.f16.f32 " \
        "{%0,%1,%2,%3}, {%4,%5,%6,%7}, {%8,%9}, {%0,%1,%2,%3};" \
        : "+f"((c)[0]), "+f"((c)[1]), "+f"((c)[2]), "+f"((c)[3]) \
        : "r"((a)[0]), "r"((a)[1]), "r"((a)[2]), "r"((a)[3]), "r"(b0), "r"(b1))

constexpr int STAGE_BYTES = 16384;              // A 8KB + B 8KB
constexpr int MMA_SMEM    = 4 * STAGE_BYTES;    // 64 KB

template <bool BIAS, bool AL>
__global__ void __launch_bounds__(128, 2)
k_mma_gemm(const __half* __restrict__ A, const __half* __restrict__ B,
           const float* __restrict__ bias, float* __restrict__ outF,
           __half* __restrict__ outH, const float* __restrict__ asv,
           const float* __restrict__ adv, int Mv, int K, int ldo, int m_base) {
    extern __shared__ char smem[];
    const uint32_t sb = s2u(smem);
    const int tid  = threadIdx.x;
    const int lane = tid & 31, wid = tid >> 5;
    const int wm = (wid & 1) * 64, wn = (wid >> 1) * 64;
    const int bm = m_base + blockIdx.x * 128, bn = blockIdx.y * 128;
    const int KITER = K >> 5;

    const __half* ag0 = A + (size_t)bm * K;
    const __half* bg0 = B + (size_t)bn * K;

    auto load_stage = [&](int kt, int slot) {
        const int k0 = kt * 32;
        const uint32_t sa  = sb + slot * STAGE_BYTES;
        const uint32_t sbm = sa + 8192;
#pragma unroll
        for (int i = 0; i < 4; i++) {
            int u = tid + i * 128;
            int row = u >> 2, seg = u & 3;
            uint32_t off = row * 64 + ((seg ^ ((row >> 1) & 3)) << 4);
            cp16(sa  + off, ag0 + (size_t)row * K + k0 + seg * 8);
            cp16(sbm + off, bg0 + (size_t)row * K + k0 + seg * 8);
        }
    };

    float acc[4][8][4];
#pragma unroll
    for (int i = 0; i < 4; i++)
#pragma unroll
        for (int j = 0; j < 8; j++)
#pragma unroll
            for (int r = 0; r < 4; r++) acc[i][j][r] = 0.f;

    load_stage(0, 0);
    asm volatile("cp.async.commit_group;" ::: "memory");
    load_stage(1, 1);
    asm volatile("cp.async.commit_group;" ::: "memory");
    load_stage(2, 2);
    asm volatile("cp.async.commit_group;" ::: "memory");

    for (int kt = 0; kt < KITER; kt++) {
        asm volatile("cp.async.wait_group 2;" ::: "memory");
        __syncthreads();
        if (kt + 3 < KITER) load_stage(kt + 3, (kt + 3) & 3);
        asm volatile("cp.async.commit_group;" ::: "memory");

        const uint32_t sa  = sb + (kt & 3) * STAGE_BYTES;
        const uint32_t sbm = sa + 8192;
#pragma unroll
        for (int ks2 = 0; ks2 < 2; ks2++) {
            uint32_t av[4][4], bv[4][4];
            const int segk = ks2 * 2 + (lane >> 4);
#pragma unroll
            for (int mf = 0; mf < 4; mf++) {
                int row = wm + mf * 16 + (lane & 15);
                LDSM4(av[mf], sa + row * 64 + ((segk ^ ((row >> 1) & 3)) << 4));
            }
#pragma unroll
            for (int p = 0; p < 4; p++) {
                int row = wn + p * 16 + (lane & 15);
                LDSM4(bv[p], sbm + row * 64 + ((segk ^ ((row >> 1) & 3)) << 4));
            }
#pragma unroll
            for (int mf = 0; mf < 4; mf++)
#pragma unroll
                for (int p = 0; p < 4; p++) {
                    MMA16816(acc[mf][p * 2 + 0], av[mf], bv[p][0], bv[p][2]);
                    MMA16816(acc[mf][p * 2 + 1], av[mf], bv[p][1], bv[p][3]);
                }
        }
    }

    // epilogue
    const int r0 = lane >> 2, c0 = (lane & 3) * 2;

    float avv[8][2], dvv[8][2];
    if (AL) {
#pragma unroll
        for (int nf = 0; nf < 8; nf++) {
            int nn = bn + wn + nf * 8 + c0;
            avv[nf][0] = __ldg(asv + nn); avv[nf][1] = __ldg(asv + nn + 1);
            dvv[nf][0] = __ldg(adv + nn); dvv[nf][1] = __ldg(adv + nn + 1);
        }
    }
    const int head = (bn + wn) >> 8;   // 64-col warp tile lies in one head

#pragma unroll
    for (int mf = 0; mf < 4; mf++) {
#pragma unroll
        for (int half = 0; half < 2; half++) {
            int m = bm + wm + mf * 16 + r0 + half * 8;
            float pa = 0.f, pd = 0.f;
            if (m < Mv) {
#pragma unroll
                for (int nf = 0; nf < 8; nf++) {
                    int n = bn + wn + nf * 8 + c0;
                    float vx = acc[mf][nf][half * 2 + 0];
                    float vy = acc[mf][nf][half * 2 + 1];
                    if (AL) {
                        pa += vx * avv[nf][0] + vy * avv[nf][1];
                        pd += vx * dvv[nf][0] + vy * dvv[nf][1];
                    }
                    if (BIAS) {
                        vx += __ldg(bias + n); vy += __ldg(bias + n + 1);
                        *reinterpret_cast<float2*>(outF + (size_t)m * ldo + n) =
                            make_float2(vx, vy);
                    } else {
                        *reinterpret_cast<__half2*>(outH + (size_t)m * ldo + n) =
                            __floats2half2_rn(vx, vy);
                    }
                }
            }
            if (AL) {
                pa += __shfl_xor_sync(0xffffffffu, pa, 1);
                pa += __shfl_xor_sync(0xffffffffu, pa, 2);
                pd += __shfl_xor_sync(0xffffffffu, pd, 1);
                pd += __shfl_xor_sync(0xffffffffu, pd, 2);
                if ((lane & 3) == 0 && m < Mv) {
                    atomicAdd(&g_al_src[m * H_ + head], pa);
                    atomicAdd(&g_al_dst[m * H_ + head], pd);
                }
            }
        }
    }
}

// ---------------- launch -----------------------------------------------------
extern "C" void kernel_launch(void* const* d_in, const int* in_sizes, int n_in,
                              void* d_out, int out_size) {
    const float* x      = (const float*)d_in[0];
    const int*   ei     = (const int*)d_in[1];
    const float* ef     = (const float*)d_in[2];
    const float* W1     = (const float*)d_in[3];
    const float* asrc1  = (const float*)d_in[4];
    const float* adst1  = (const float*)d_in[5];
    const float* aedge1 = (const float*)d_in[6];
    const float* We1    = (const float*)d_in[7];
    const float* b1     = (const float*)d_in[8];
    const float* W2     = (const float*)d_in[9];
    const float* asrc2  = (const float*)d_in[10];
    const float* adst2  = (const float*)d_in[11];
    const float* aedge2 = (const float*)d_in[12];
    const float* We2    = (const float*)d_in[13];
    const float* b2     = (const float*)d_in[14];
    const float* Wf     = (const float*)d_in[15];
    const float* bf     = (const float*)d_in[16];
    const int* src = ei;
    const int* dst = ei + NE;
    float* out = (float*)d_out;

    void* p;
    cudaGetSymbolAddress(&p, g_xw2); __half* xw2 = (__half*)p;
    cudaGetSymbolAddress(&p, g_Asp); __half* Asp = (__half*)p;
    cudaGetSymbolAddress(&p, g_BtF); __half* BtF = (__half*)p;
    cudaGetSymbolAddress(&p, g_Bt2); __half* Bt2 = (__half*)p;
    cudaGetSymbolAddress(&p, g_Bt1); __half* Bt1 = (__half*)p;
    cudaGetSymbolAddress(&p, g_V1);  float* V1  = (float*)p;
    cudaGetSymbolAddress(&p, g_V2);  float* V2  = (float*)p;
    cudaGetSymbolAddress(&p, g_s1);  float* s1p = (float*)p;
    cudaGetSymbolAddress(&p, g_s2);  float* s2p = (float*)p;

    static bool init_done = false;
    static cudaStream_t s1;
    static cudaEvent_t evFork, evB12, evPre, evBF, evG2, evAggB;
    if (!init_done) {
        cudaFuncSetAttribute((const void*)k_mma_gemm<true, false>,
                             cudaFuncAttributeMaxDynamicSharedMemorySize, MMA_SMEM);
        cudaFuncSetAttribute((const void*)k_mma_gemm<false, true>,
                             cudaFuncAttributeMaxDynamicSharedMemorySize, MMA_SMEM);
        cudaStreamCreateWithFlags(&s1, cudaStreamNonBlocking);
        cudaEventCreateWithFlags(&evFork, cudaEventDisableTiming);
        cudaEventCreateWithFlags(&evB12,  cudaEventDisableTiming);
        cudaEventCreateWithFlags(&evPre,  cudaEventDisableTiming);
        cudaEventCreateWithFlags(&evBF,   cudaEventDisableTiming);
        cudaEventCreateWithFlags(&evG2,   cudaEventDisableTiming);
        cudaEventCreateWithFlags(&evAggB, cudaEventDisableTiming);
        init_done = true;
    }

    // fork side stream
    cudaEventRecord(evFork, 0);
    cudaStreamWaitEvent(s1, evFork, 0);

    // side: layer weights first (GEMM1 needs Bt1)
    k_convB<<<dim3(HC / 32, DIN / 32), dim3(32, 32), 0, s1>>>(W1, Bt1, DIN, HC);
    k_convB<<<dim3(HC / 32, HC / 32), dim3(32, 32), 0, s1>>>(W2, Bt2, HC, HC);
    cudaEventRecord(evB12, s1);
    // side: V's + CSR + edge prep (layer-activation independent)
    k_V<<<1, 256, 0, s1>>>(We1, aedge1, V1);
    k_V<<<1, 256, 0, s1>>>(We2, aedge2, V2);
    k_zero_deg<<<(NN + 255) / 256, 256, 0, s1>>>();
    k_count<<<(NE + 255) / 256, 256, 0, s1>>>(dst);
    k_scanA<<<40, 256, 0, s1>>>();
    k_scanB<<<1, 64, 0, s1>>>();
    k_scanC<<<40, 256, 0, s1>>>();
    k_fill<<<(NE + 255) / 256, 256, 0, s1>>>(dst);
    k_edgeprep<<<(NE + 255) / 256, 256, 0, s1>>>(ef, src);
    cudaEventRecord(evPre, s1);
    // side: big final-weight conversion
    k_convB<<<dim3(DOUT / 32, HC / 32), dim3(32, 32), 0, s1>>>(Wf, BtF, HC, DOUT);
    cudaEventRecord(evBF, s1);

    // main: layer-1 A conversion + al zeroing overlap all of the above
    k_convA<<<(MPAD * DIN + 255) / 256, 256>>>(x, Asp, NN, DIN);
    k_zero_al<<<(NN * H_ + 255) / 256, 256>>>();

    // ---- layer 1 (GEMM fuses al accumulation) ----
    cudaStreamWaitEvent(0, evB12, 0);
    k_mma_gemm<false, true><<<dim3(MPAD / 128, HC / 128), 128, MMA_SMEM>>>(
        Asp, Bt1, nullptr, nullptr, xw2, asrc1, adst1, NN, DIN, HC, 0);
    cudaStreamWaitEvent(0, evPre, 0);
    k_aggregate<<<NN, 256>>>(xw2, s1p, b1, Asp, 0);

    // ---- layer 2 ----
    k_zero_al<<<(NN * H_ + 255) / 256, 256>>>();
    k_mma_gemm<false, true><<<dim3(MPAD / 128, HC / 128), 128, MMA_SMEM>>>(
        Asp, Bt2, nullptr, nullptr, xw2, asrc2, adst2, NN, HC, HC, 0);
    cudaEventRecord(evG2, 0);

    // side: aggregate2 upper node range (overlaps lower range + GEMMF half 1)
    cudaStreamWaitEvent(s1, evG2, 0);
    k_aggregate<<<NN - NSPL, 256, 0, s1>>>(xw2, s2p, b2, Asp, NSPL);
    cudaEventRecord(evAggB, s1);

    // main: aggregate2 lower node range, then final GEMM half 1 (m 0..NSPL)
    k_aggregate<<<NSPL, 256>>>(xw2, s2p, b2, Asp, 0);
    cudaStreamWaitEvent(0, evBF, 0);
    k_mma_gemm<true, false><<<dim3(NSPL / 128, DOUT / 128), 128, MMA_SMEM>>>(
        Asp, BtF, bf, out, nullptr, nullptr, nullptr, NN, HC, DOUT, 0);

    // main: final GEMM half 2 (m NSPL..MPAD) after side aggregate completes
    cudaStreamWaitEvent(0, evAggB, 0);
    k_mma_gemm<true, false><<<dim3((MPAD - NSPL) / 128, DOUT / 128), 128, MMA_SMEM>>>(
        Asp, BtF, bf, out, nullptr, nullptr, nullptr, NN, HC, DOUT, NSPL);
}

// round 17
// speedup vs baseline: 1.0045x; 1.0045x over previous
#include <cuda_runtime.h>
#include <cuda_fp16.h>
#include <math.h>
#include <stdint.h>

// Problem constants (fixed shapes per metadata)
constexpr int NN   = 10000;   // nodes
constexpr int NE   = 160000;  // edges
constexpr int DIN  = 128;     // input feature dim
constexpr int EDIM = 16;      // edge feature dim
constexpr int H_   = 4;       // heads
constexpr int C_   = 256;     // channels per head
constexpr int HC   = 1024;    // H*C
constexpr int DOUT = 25088;   // final output dim

constexpr int MPAD = 10112;   // 79 * 128 (M padded)

// ---------------- scratch (static device globals: allocation-free) ----------
__device__ __half g_xw2[NN * HC];         // layer GEMM output (fp16)
__device__ float  g_al_src[NN * H_];
__device__ float  g_al_dst[NN * H_];
__device__ float  g_exp_s[(size_t)H_ * NE];    // exp(alpha-max), SoA CSR-sorted
__device__ float  g_s1[(size_t)H_ * NE];       // raw edge logits layer1 (SoA)
__device__ float  g_s2[(size_t)H_ * NE];       // raw edge logits layer2 (SoA)
__device__ float  g_V1[EDIM * H_];
__device__ float  g_V2[EDIM * H_];
__device__ int    g_deg[NN];
__device__ int    g_rowptr[NN + 1];
__device__ int    g_cursor[NN];
__device__ int    g_esorted[NE];
__device__ int    g_src_s[NE];            // src node per sorted position
__device__ int    g_bsum[40];
__device__ int    g_boff[40];
__device__ __half g_Asp[(size_t)MPAD * HC];     // GEMM A operand (fp16)
__device__ __half g_BtF[(size_t)DOUT * HC];     // Wf^T fp16 [25088,1024]
__device__ __half g_Bt2[(size_t)HC * HC];       // W2^T fp16 [1024,1024]
__device__ __half g_Bt1[(size_t)HC * DIN];      // W1^T fp16 [1024,128]

// ---------------- graph structure kernels ----------------------------------
__global__ void k_zero_deg() {
    int i = blockIdx.x * blockDim.x + threadIdx.x;
    if (i < NN) g_deg[i] = 0;
}

__global__ void k_zero_al() {
    int i = blockIdx.x * blockDim.x + threadIdx.x;
    if (i < NN * H_) { g_al_src[i] = 0.f; g_al_dst[i] = 0.f; }
}

__global__ void k_count(const int* __restrict__ dst) {
    int e = blockIdx.x * blockDim.x + threadIdx.x;
    if (e < NE) atomicAdd(&g_deg[dst[e]], 1);
}

// 3-stage parallel scan of g_deg -> g_rowptr/g_cursor
__global__ void k_scanA() {
    __shared__ int sh[256];
    int i = blockIdx.x * 256 + threadIdx.x;
    sh[threadIdx.x] = (i < NN) ? g_deg[i] : 0;
    __syncthreads();
    for (int off = 128; off; off >>= 1) {
        if (threadIdx.x < off) sh[threadIdx.x] += sh[threadIdx.x + off];
        __syncthreads();
    }
    if (threadIdx.x == 0) g_bsum[blockIdx.x] = sh[0];
}

__global__ void k_scanB() {
    __shared__ int sh[64];
    int t = threadIdx.x;
    int v = (t < 40) ? g_bsum[t] : 0;
    sh[t] = v;
    __syncthreads();
    for (int off = 1; off < 64; off <<= 1) {
        int x = (t >= off) ? sh[t - off] : 0;
        __syncthreads();
        sh[t] += x;
        __syncthreads();
    }
    if (t < 40) g_boff[t] = sh[t] - v;
    if (t == 39) g_rowptr[NN] = sh[39];
}

__global__ void k_scanC() {
    __shared__ int sh[256];
    int i = blockIdx.x * 256 + threadIdx.x;
    int v = (i < NN) ? g_deg[i] : 0;
    sh[threadIdx.x] = v;
    __syncthreads();
    for (int off = 1; off < 256; off <<= 1) {
        int x = (threadIdx.x >= off) ? sh[threadIdx.x - off] : 0;
        __syncthreads();
        sh[threadIdx.x] += x;
        __syncthreads();
    }
    if (i < NN) {
        int excl = sh[threadIdx.x] - v + g_boff[blockIdx.x];
        g_rowptr[i] = excl;
        g_cursor[i] = excl;
    }
}

__global__ void k_fill(const int* __restrict__ dst) {
    int e = blockIdx.x * blockDim.x + threadIdx.x;
    if (e < NE) {
        int p = atomicAdd(&g_cursor[dst[e]], 1);
        g_esorted[p] = e;
    }
}

// ---------------- attention logit pieces ------------------------------------
__global__ void k_V(const float* __restrict__ We, const float* __restrict__ aedge,
                    float* __restrict__ Vout) {
    int w = threadIdx.x >> 5, l = threadIdx.x & 31;
    for (int o = w; o < EDIM * H_; o += 8) {
        int d = o / H_, h = o % H_;
        float s = 0.f;
        for (int c = l; c < C_; c += 32)
            s += We[(size_t)d * HC + h * C_ + c] * aedge[h * C_ + c];
#pragma unroll
        for (int off = 16; off; off >>= 1) s += __shfl_xor_sync(0xffffffffu, s, off);
        if (l == 0) Vout[o] = s;
    }
}

// One pass over CSR-sorted positions (layer-independent): gathers edge
// features once, emits src ids + raw edge logits for BOTH layers.
__global__ void k_edgeprep(const float* __restrict__ ef, const int* __restrict__ src) {
    __shared__ float sV1[EDIM * H_], sV2[EDIM * H_];
    if (threadIdx.x < EDIM * H_) {
        sV1[threadIdx.x] = g_V1[threadIdx.x];
        sV2[threadIdx.x] = g_V2[threadIdx.x];
    }
    __syncthreads();
    int i = blockIdx.x * blockDim.x + threadIdx.x;
    if (i >= NE) return;
    int e  = g_esorted[i];
    g_src_s[i] = src[e];
    float ea[EDIM];
    const float4* efp = reinterpret_cast<const float4*>(ef + (size_t)e * EDIM);
#pragma unroll
    for (int q = 0; q < EDIM / 4; q++) {
        float4 v = efp[q];
        ea[q * 4 + 0] = v.x; ea[q * 4 + 1] = v.y; ea[q * 4 + 2] = v.z; ea[q * 4 + 3] = v.w;
    }
#pragma unroll
    for (int h = 0; h < H_; h++) {
        float s1 = 0.f, s2 = 0.f;
#pragma unroll
        for (int d = 0; d < EDIM; d++) {
            s1 += ea[d] * sV1[d * H_ + h];
            s2 += ea[d] * sV2[d * H_ + h];
        }
        g_s1[(size_t)h * NE + i] = s1;
        g_s2[(size_t)h * NE + i] = s2;
    }
}

// ---------------- segment softmax + aggregation (1 block / node) ------------
// Alpha recomputed from raw logits on the fly.  8 warps: warp w handles head
// (w&3), slice (w>>2) in phases 0-2; phase 3 channel-parallel, 2-way unrolled.
__global__ void __launch_bounds__(256)
k_aggregate(const __half* __restrict__ xw2, const float* __restrict__ sL,
            const float* __restrict__ bias, __half* __restrict__ outH) {
    int n = blockIdx.x;
    int beg = g_rowptr[n], end = g_rowptr[n + 1];
    __shared__ float sm[H_], ss[H_], sself[H_];
    __shared__ float p_es[2][H_], p_mx[2][H_], p_ac[2][H_];
    int t = threadIdx.x, w = t >> 5, l = t & 31;
    const int hh = w & 3, sl = w >> 2;

    // phase 0+1 fused: esum (raw s) + max (leaky alpha) over this warp's slice
    {
        const float* ssrc = sL + (size_t)hh * NE;
        const float ald = g_al_dst[n * H_ + hh];
        float es = 0.f, mx = -1e30f;
        for (int i = beg + l + 32 * sl; i < end; i += 64) {
            float s = ssrc[i];
            es += s;
            float a = g_al_src[g_src_s[i] * H_ + hh] + ald + s;
            a = a > 0.f ? a : 0.2f * a;
            mx = fmaxf(mx, a);
        }
#pragma unroll
        for (int off = 16; off; off >>= 1) {
            es += __shfl_xor_sync(0xffffffffu, es, off);
            mx = fmaxf(mx, __shfl_xor_sync(0xffffffffu, mx, off));
        }
        if (l == 0) { p_es[sl][hh] = es; p_mx[sl][hh] = mx; }
    }
    __syncthreads();
    if (t < H_) {
        float es = p_es[0][t] + p_es[1][t];
        float mx = fmaxf(p_mx[0][t], p_mx[1][t]);
        float invd = 1.0f / fmaxf((float)(end - beg), 1.0f);
        float v = g_al_src[n * H_ + t] + g_al_dst[n * H_ + t] + es * invd;
        v = v > 0.f ? v : 0.2f * v;
        sself[t] = v;
        sm[t] = fmaxf(mx, v);
    }
    __syncthreads();

    // phase 2: recompute alpha, exp, store exp; accumulate sum over slice
    {
        float mm = sm[hh];
        const float* ssrc = sL + (size_t)hh * NE;
        const float ald = g_al_dst[n * H_ + hh];
        float* ex_out = g_exp_s + (size_t)hh * NE;
        float acc = 0.f;
        for (int i = beg + l + 32 * sl; i < end; i += 64) {
            float a = g_al_src[g_src_s[i] * H_ + hh] + ald + ssrc[i];
            a = a > 0.f ? a : 0.2f * a;
            float ex = expf(a - mm);
            ex_out[i] = ex;
            acc += ex;
        }
#pragma unroll
        for (int off = 16; off; off >>= 1) acc += __shfl_xor_sync(0xffffffffu, acc, off);
        if (l == 0) p_ac[sl][hh] = acc;
    }
    __syncthreads();
    if (t < H_)
        ss[t] = p_ac[0][t] + p_ac[1][t] + expf(sself[t] - sm[t]);
    __syncthreads();

    // phase 3: weighted gather, 2-way unrolled (dual dependency chains).
    const int h = t >> 6;
    const float inv = 1.0f / (ss[h] + 1e-16f);
    const float* exh = g_exp_s + (size_t)h * NE;
    float a0 = 0.f, a1 = 0.f, a2 = 0.f, a3 = 0.f;
    float b0 = 0.f, b1v = 0.f, b2v = 0.f, b3 = 0.f;
    int i = beg;
    for (; i + 1 < end; i += 2) {
        int sn0 = g_src_s[i], sn1 = g_src_s[i + 1];
        float w0 = exh[i], w1 = exh[i + 1];
        uint2 r0 = *reinterpret_cast<const uint2*>(xw2 + (size_t)sn0 * HC + 4 * t);
        uint2 r1 = *reinterpret_cast<const uint2*>(xw2 + (size_t)sn1 * HC + 4 * t);
        __half2 p00 = *reinterpret_cast<__half2*>(&r0.x);
        __half2 p01 = *reinterpret_cast<__half2*>(&r0.y);
        __half2 p10 = *reinterpret_cast<__half2*>(&r1.x);
        __half2 p11 = *reinterpret_cast<__half2*>(&r1.y);
        a0 += w0 * __low2float(p00); a1 += w0 * __high2float(p00);
        a2 += w0 * __low2float(p01); a3 += w0 * __high2float(p01);
        b0 += w1 * __low2float(p10); b1v += w1 * __high2float(p10);
        b2v += w1 * __low2float(p11); b3 += w1 * __high2float(p11);
    }
    if (i < end) {
        int sn = g_src_s[i];
        float wg = exh[i];
        uint2 rv = *reinterpret_cast<const uint2*>(xw2 + (size_t)sn * HC + 4 * t);
        __half2 p0 = *reinterpret_cast<__half2*>(&rv.x);
        __half2 p1 = *reinterpret_cast<__half2*>(&rv.y);
        a0 += wg * __low2float(p0); a1 += wg * __high2float(p0);
        a2 += wg * __low2float(p1); a3 += wg * __high2float(p1);
    }
    {   // self loop
        float wg = expf(sself[h] - sm[h]);
        uint2 rv = *reinterpret_cast<const uint2*>(xw2 + (size_t)n * HC + 4 * t);
        __half2 p0 = *reinterpret_cast<__half2*>(&rv.x);
        __half2 p1 = *reinterpret_cast<__half2*>(&rv.y);
        a0 += wg * __low2float(p0); a1 += wg * __high2float(p0);
        a2 += wg * __low2float(p1); a3 += wg * __high2float(p1);
    }
    a0 += b0; a1 += b1v; a2 += b2v; a3 += b3;
    float4 b4 = *reinterpret_cast<const float4*>(bias + 4 * t);
    float v0 = a0 * inv + b4.x, v1 = a1 * inv + b4.y;
    float v2 = a2 * inv + b4.z, v3 = a3 * inv + b4.w;
    v0 = v0 > 0.f ? v0 : expm1f(v0);
    v1 = v1 > 0.f ? v1 : expm1f(v1);
    v2 = v2 > 0.f ? v2 : expm1f(v2);
    v3 = v3 > 0.f ? v3 : expm1f(v3);
    uint2 ov;
    *reinterpret_cast<__half2*>(&ov.x) = __floats2half2_rn(v0, v1);
    *reinterpret_cast<__half2*>(&ov.y) = __floats2half2_rn(v2, v3);
    *reinterpret_cast<uint2*>(outH + (size_t)n * HC + 4 * t) = ov;
}

// ---------------- fp16 conversions ------------------------------------------
__global__ void k_convA(const float* __restrict__ src, __half* __restrict__ dst,
                        int Mv, int K) {
    int i = blockIdx.x * blockDim.x + threadIdx.x;
    if (i >= MPAD * K) return;
    int m = i / K, k = i - m * K;
    float a = (m < Mv) ? src[(size_t)m * K + k] : 0.f;
    dst[(size_t)m * K + k] = __float2half(a);
}

__global__ void k_convB(const float* __restrict__ W, __half* __restrict__ dst,
                        int K, int Nn) {
    __shared__ float t[32][33];
    int n = blockIdx.x * 32 + threadIdx.x;
    int k = blockIdx.y * 32 + threadIdx.y;
    t[threadIdx.y][threadIdx.x] = W[(size_t)k * Nn + n];
    __syncthreads();
    int n2 = blockIdx.x * 32 + threadIdx.y;
    int k2 = blockIdx.y * 32 + threadIdx.x;
    dst[(size_t)n2 * K + k2] = __float2half(t[threadIdx.x][threadIdx.y]);
}

// ---------------- fp16 HMMA GEMM --------------------------------------------
// CTA tile 128x128, 128 threads (4 warps, warp tile 64x64), BK=32,
// 4-stage cp.async pipeline (64 KB smem), 2 CTAs/SM.
// AL=true fuses al_src/al_dst accumulation into the epilogue.

__device__ __forceinline__ uint32_t s2u(const void* p) {
    uint32_t a;
    asm("{ .reg .u64 t; cvta.to.shared.u64 t, %1; cvt.u32.u64 %0, t; }" : "=r"(a) : "l"(p));
    return a;
}

__device__ __forceinline__ void cp16(uint32_t saddr, const void* gptr) {
    asm volatile("cp.async.cg.shared.global [%0], [%1], 16;" :: "r"(saddr), "l"(gptr));
}

#define LDSM4(r, addr) \
    asm volatile("ldmatrix.sync.aligned.m8n8.x4.shared.b16 {%0,%1,%2,%3}, [%4];" \
        : "=r"((r)[0]), "=r"((r)[1]), "=r"((r)[2]), "=r"((r)[3]) : "r"(addr))

#define MMA16816(c, a, b0, b1) \
    asm volatile("mma.sync.aligned.m16n8k16.row.col.f32.f16.f16.f32 " \
        "{%0,%1,%2,%3}, {%4,%5,%6,%7}, {%8,%9}, {%0,%1,%2,%3};" \
        : "+f"((c)[0]), "+f"((c)[1]), "+f"((c)[2]), "+f"((c)[3]) \
        : "r"((a)[0]), "r"((a)[1]), "r"((a)[2]), "r"((a)[3]), "r"(b0), "r"(b1))

constexpr int STAGE_BYTES = 16384;              // A 8KB + B 8KB
constexpr int MMA_SMEM    = 4 * STAGE_BYTES;    // 64 KB

template <bool BIAS, bool AL>
__global__ void __launch_bounds__(128, 2)
k_mma_gemm(const __half* __restrict__ A, const __half* __restrict__ B,
           const float* __restrict__ bias, float* __restrict__ outF,
           __half* __restrict__ outH, const float* __restrict__ asv,
           const float* __restrict__ adv, int Mv, int K, int ldo) {
    extern __shared__ char smem[];
    const uint32_t sb = s2u(smem);
    const int tid  = threadIdx.x;
    const int lane = tid & 31, wid = tid >> 5;
    const int wm = (wid & 1) * 64, wn = (wid >> 1) * 64;
    const int bm = blockIdx.x * 128, bn = blockIdx.y * 128;
    const int KITER = K >> 5;

    const __half* ag0 = A + (size_t)bm * K;
    const __half* bg0 = B + (size_t)bn * K;

    auto load_stage = [&](int kt, int slot) {
        const int k0 = kt * 32;
        const uint32_t sa  = sb + slot * STAGE_BYTES;
        const uint32_t sbm = sa + 8192;
#pragma unroll
        for (int i = 0; i < 4; i++) {
            int u = tid + i * 128;
            int row = u >> 2, seg = u & 3;
            uint32_t off = row * 64 + ((seg ^ ((row >> 1) & 3)) << 4);
            cp16(sa  + off, ag0 + (size_t)row * K + k0 + seg * 8);
            cp16(sbm + off, bg0 + (size_t)row * K + k0 + seg * 8);
        }
    };

    float acc[4][8][4];
#pragma unroll
    for (int i = 0; i < 4; i++)
#pragma unroll
        for (int j = 0; j < 8; j++)
#pragma unroll
            for (int r = 0; r < 4; r++) acc[i][j][r] = 0.f;

    load_stage(0, 0);
    asm volatile("cp.async.commit_group;" ::: "memory");
    load_stage(1, 1);
    asm volatile("cp.async.commit_group;" ::: "memory");
    load_stage(2, 2);
    asm volatile("cp.async.commit_group;" ::: "memory");

    for (int kt = 0; kt < KITER; kt++) {
        asm volatile("cp.async.wait_group 2;" ::: "memory");
        __syncthreads();
        if (kt + 3 < KITER) load_stage(kt + 3, (kt + 3) & 3);
        asm volatile("cp.async.commit_group;" ::: "memory");

        const uint32_t sa  = sb + (kt & 3) * STAGE_BYTES;
        const uint32_t sbm = sa + 8192;
#pragma unroll
        for (int ks2 = 0; ks2 < 2; ks2++) {
            uint32_t av[4][4], bv[4][4];
            const int segk = ks2 * 2 + (lane >> 4);
#pragma unroll
            for (int mf = 0; mf < 4; mf++) {
                int row = wm + mf * 16 + (lane & 15);
                LDSM4(av[mf], sa + row * 64 + ((segk ^ ((row >> 1) & 3)) << 4));
            }
#pragma unroll
            for (int p = 0; p < 4; p++) {
                int row = wn + p * 16 + (lane & 15);
                LDSM4(bv[p], sbm + row * 64 + ((segk ^ ((row >> 1) & 3)) << 4));
            }
#pragma unroll
            for (int mf = 0; mf < 4; mf++)
#pragma unroll
                for (int p = 0; p < 4; p++) {
                    MMA16816(acc[mf][p * 2 + 0], av[mf], bv[p][0], bv[p][2]);
                    MMA16816(acc[mf][p * 2 + 1], av[mf], bv[p][1], bv[p][3]);
                }
        }
    }

    // epilogue
    const int r0 = lane >> 2, c0 = (lane & 3) * 2;

    float avv[8][2], dvv[8][2];
    if (AL) {
#pragma unroll
        for (int nf = 0; nf < 8; nf++) {
            int nn = bn + wn + nf * 8 + c0;
            avv[nf][0] = __ldg(asv + nn); avv[nf][1] = __ldg(asv + nn + 1);
            dvv[nf][0] = __ldg(adv + nn); dvv[nf][1] = __ldg(adv + nn + 1);
        }
    }
    const int head = (bn + wn) >> 8;   // 64-col warp tile lies in one head

#pragma unroll
    for (int mf = 0; mf < 4; mf++) {
#pragma unroll
        for (int half = 0; half < 2; half++) {
            int m = bm + wm + mf * 16 + r0 + half * 8;
            float pa = 0.f, pd = 0.f;
            if (m < Mv) {
#pragma unroll
                for (int nf = 0; nf < 8; nf++) {
                    int n = bn + wn + nf * 8 + c0;
                    float vx = acc[mf][nf][half * 2 + 0];
                    float vy = acc[mf][nf][half * 2 + 1];
                    if (AL) {
                        pa += vx * avv[nf][0] + vy * avv[nf][1];
                        pd += vx * dvv[nf][0] + vy * dvv[nf][1];
                    }
                    if (BIAS) {
                        vx += __ldg(bias + n); vy += __ldg(bias + n + 1);
                        *reinterpret_cast<float2*>(outF + (size_t)m * ldo + n) =
                            make_float2(vx, vy);
                    } else {
                        *reinterpret_cast<__half2*>(outH + (size_t)m * ldo + n) =
                            __floats2half2_rn(vx, vy);
                    }
                }
            }
            if (AL) {
                pa += __shfl_xor_sync(0xffffffffu, pa, 1);
                pa += __shfl_xor_sync(0xffffffffu, pa, 2);
                pd += __shfl_xor_sync(0xffffffffu, pd, 1);
                pd += __shfl_xor_sync(0xffffffffu, pd, 2);
                if ((lane & 3) == 0 && m < Mv) {
                    atomicAdd(&g_al_src[m * H_ + head], pa);
                    atomicAdd(&g_al_dst[m * H_ + head], pd);
                }
            }
        }
    }
}

// ---------------- launch -----------------------------------------------------
extern "C" void kernel_launch(void* const* d_in, const int* in_sizes, int n_in,
                              void* d_out, int out_size) {
    const float* x      = (const float*)d_in[0];
    const int*   ei     = (const int*)d_in[1];
    const float* ef     = (const float*)d_in[2];
    const float* W1     = (const float*)d_in[3];
    const float* asrc1  = (const float*)d_in[4];
    const float* adst1  = (const float*)d_in[5];
    const float* aedge1 = (const float*)d_in[6];
    const float* We1    = (const float*)d_in[7];
    const float* b1     = (const float*)d_in[8];
    const float* W2     = (const float*)d_in[9];
    const float* asrc2  = (const float*)d_in[10];
    const float* adst2  = (const float*)d_in[11];
    const float* aedge2 = (const float*)d_in[12];
    const float* We2    = (const float*)d_in[13];
    const float* b2     = (const float*)d_in[14];
    const float* Wf     = (const float*)d_in[15];
    const float* bf     = (const float*)d_in[16];
    const int* src = ei;
    const int* dst = ei + NE;
    float* out = (float*)d_out;

    void* p;
    cudaGetSymbolAddress(&p, g_xw2); __half* xw2 = (__half*)p;
    cudaGetSymbolAddress(&p, g_Asp); __half* Asp = (__half*)p;
    cudaGetSymbolAddress(&p, g_BtF); __half* BtF = (__half*)p;
    cudaGetSymbolAddress(&p, g_Bt2); __half* Bt2 = (__half*)p;
    cudaGetSymbolAddress(&p, g_Bt1); __half* Bt1 = (__half*)p;
    cudaGetSymbolAddress(&p, g_V1);  float* V1  = (float*)p;
    cudaGetSymbolAddress(&p, g_V2);  float* V2  = (float*)p;
    cudaGetSymbolAddress(&p, g_s1);  float* s1p = (float*)p;
    cudaGetSymbolAddress(&p, g_s2);  float* s2p = (float*)p;

    static bool init_done = false;
    static cudaStream_t s1;
    static cudaEvent_t evFork, evB12, evPre, evBF;
    if (!init_done) {
        cudaFuncSetAttribute((const void*)k_mma_gemm<true, false>,
                             cudaFuncAttributeMaxDynamicSharedMemorySize, MMA_SMEM);
        cudaFuncSetAttribute((const void*)k_mma_gemm<false, true>,
                             cudaFuncAttributeMaxDynamicSharedMemorySize, MMA_SMEM);
        cudaStreamCreateWithFlags(&s1, cudaStreamNonBlocking);
        cudaEventCreateWithFlags(&evFork, cudaEventDisableTiming);
        cudaEventCreateWithFlags(&evB12,  cudaEventDisableTiming);
        cudaEventCreateWithFlags(&evPre,  cudaEventDisableTiming);
        cudaEventCreateWithFlags(&evBF,   cudaEventDisableTiming);
        init_done = true;
    }

    // fork side stream
    cudaEventRecord(evFork, 0);
    cudaStreamWaitEvent(s1, evFork, 0);

    // side: layer weights first (GEMM1 needs Bt1)
    k_convB<<<dim3(HC / 32, DIN / 32), dim3(32, 32), 0, s1>>>(W1, Bt1, DIN, HC);
    k_convB<<<dim3(HC / 32, HC / 32), dim3(32, 32), 0, s1>>>(W2, Bt2, HC, HC);
    cudaEventRecord(evB12, s1);
    // side: V's + CSR + edge prep (layer-activation independent)
    k_V<<<1, 256, 0, s1>>>(We1, aedge1, V1);
    k_V<<<1, 256, 0, s1>>>(We2, aedge2, V2);
    k_zero_deg<<<(NN + 255) / 256, 256, 0, s1>>>();
    k_count<<<(NE + 255) / 256, 256, 0, s1>>>(dst);
    k_scanA<<<40, 256, 0, s1>>>();
    k_scanB<<<1, 64, 0, s1>>>();
    k_scanC<<<40, 256, 0, s1>>>();
    k_fill<<<(NE + 255) / 256, 256, 0, s1>>>(dst);
    k_edgeprep<<<(NE + 255) / 256, 256, 0, s1>>>(ef, src);
    cudaEventRecord(evPre, s1);
    // side: big final-weight conversion (joins before final GEMM)
    k_convB<<<dim3(DOUT / 32, HC / 32), dim3(32, 32), 0, s1>>>(Wf, BtF, HC, DOUT);
    cudaEventRecord(evBF, s1);

    // main: layer-1 A conversion + al zeroing overlap all of the above
    k_convA<<<(MPAD * DIN + 255) / 256, 256>>>(x, Asp, NN, DIN);
    k_zero_al<<<(NN * H_ + 255) / 256, 256>>>();

    // ---- layer 1 (GEMM fuses al_src/al_dst accumulation) ----
    cudaStreamWaitEvent(0, evB12, 0);
    k_mma_gemm<false, true><<<dim3(MPAD / 128, HC / 128), 128, MMA_SMEM>>>(
        Asp, Bt1, nullptr, nullptr, xw2, asrc1, adst1, NN, DIN, HC);
    cudaStreamWaitEvent(0, evPre, 0);
    k_aggregate<<<NN, 256>>>(xw2, s1p, b1, Asp);

    // ---- layer 2 ----
    k_zero_al<<<(NN * H_ + 255) / 256, 256>>>();
    k_mma_gemm<false, true><<<dim3(MPAD / 128, HC / 128), 128, MMA_SMEM>>>(
        Asp, Bt2, nullptr, nullptr, xw2, asrc2, adst2, NN, HC, HC);
    k_aggregate<<<NN, 256>>>(xw2, s2p, b2, Asp);

    // ---- final linear: out = h2 @ Wf + bf ----
    cudaStreamWaitEvent(0, evBF, 0);
    k_mma_gemm<true, false><<<dim3(MPAD / 128, DOUT / 128), 128, MMA_SMEM>>>(
        Asp, BtF, bf, out, nullptr, nullptr, nullptr, NN, HC, DOUT);
}